// round 4
// baseline (speedup 1.0000x reference)
#include <cuda_runtime.h>

// SlidingMean fused: out = (x - boxfilter_79x69(x)) / 5, SAME (zero) padding.
// One kernel. Each block produces a 64-row x 512-col stripe as 4 sub-stripes
// of 16 rows, carrying the vertical 79-tap sliding sum across sub-stripes
// (one 79-row init per 64 rows -> 3.2x read amp instead of 5.9x).
// Double-buffered smem: one barrier per sub-stripe. Horizontal window via
// per-warp register prefix scan (5 shfls) + swizzled smem taps.

#define HH 512
#define WW 512
#define NB 32
#define KH 79
#define KW 69
#define RH 39   // (KH-1)/2
#define RW 34   // (KW-1)/2
#define TH 16   // rows per sub-stripe (1 row per warp in phase B)
#define NSUB 4
#define CH (TH * NSUB)   // 64 rows per block

// XOR swizzle on 16B units within a 2KB row: conflict-free for scalar stores
// at consecutive elements, float4 loads at unit 4*lane, and (near) conflict-free
// scalar tap loads at consecutive elements.
__device__ __forceinline__ int swz(int e) {
    int u = e >> 2;
    int pu = u ^ ((u >> 3) & 7);
    return (pu << 2) | (e & 3);
}

// Phase B + epilogue for one 16-row sub-stripe held in `buf` (swizzled colsums).
// Warp w owns row w. In-place prefix scan, then windowed diff + normalize.
__device__ __forceinline__ void scan_and_epilogue(float* __restrict__ buf,
                                                  const float* __restrict__ x,
                                                  float* __restrict__ out,
                                                  size_t gbase, int hrow0,
                                                  int lane, int wrp) {
    const unsigned FULL = 0xffffffffu;
    float* __restrict__ row = buf + (wrp << 9);

    // load 16 contiguous elements (16*lane .. 16*lane+15) via 4 swizzled float4
    float p[16];
    #pragma unroll
    for (int c = 0; c < 4; ++c) {
        int u = (lane << 2) + c;
        int pu = u ^ ((u >> 3) & 7);
        float4 v = *reinterpret_cast<const float4*>(row + (pu << 2));
        p[c * 4 + 0] = v.x; p[c * 4 + 1] = v.y; p[c * 4 + 2] = v.z; p[c * 4 + 3] = v.w;
    }
    #pragma unroll
    for (int j = 1; j < 16; ++j) p[j] += p[j - 1];
    float tot = p[15];
    float inc = tot;
    #pragma unroll
    for (int off = 1; off < 32; off <<= 1) {
        float u = __shfl_up_sync(FULL, inc, off);
        if (lane >= off) inc += u;
    }
    float excl = inc - tot;
    #pragma unroll
    for (int j = 0; j < 16; ++j) p[j] += excl;
    #pragma unroll
    for (int c = 0; c < 4; ++c) {
        int u = (lane << 2) + c;
        int pu = u ^ ((u >> 3) & 7);
        *reinterpret_cast<float4*>(row + (pu << 2)) =
            make_float4(p[c * 4 + 0], p[c * 4 + 1], p[c * 4 + 2], p[c * 4 + 3]);
    }
    __syncwarp();  // only this warp touches this row

    const float inv_cnt = 1.0f / (float)(KH * KW);
    const float inv_std = 0.2f;  // 1/5
    const size_t rbase = gbase + (size_t)(hrow0 + wrp) * WW;
    #pragma unroll
    for (int i = 0; i < 16; ++i) {
        int w = lane + (i << 5);
        int hiI = w + RW; if (hiI > WW - 1) hiI = WW - 1;
        int loI = w - RW - 1;
        float hi = row[swz(hiI)];
        float lo = (loI >= 0) ? row[swz(loI)] : 0.0f;
        float winsum = hi - lo;
        size_t o = rbase + w;
        out[o] = (x[o] - winsum * inv_cnt) * inv_std;
    }
}

__global__ __launch_bounds__(512) void sliding_mean_fused(const float* __restrict__ x,
                                                          float* __restrict__ out) {
    extern __shared__ float smemC[];   // 2 buffers of [TH][WW] (swizzled)

    const int blk = blockIdx.x;
    const int hc = blk & 7;            // 8 chunks of 64 rows
    const int n  = blk >> 3;           // batch
    const int h0 = hc * CH;
    const int t  = threadIdx.x;        // column index in phase A
    const int lane = t & 31;
    const int wrp  = t >> 5;

    const size_t gbase = (size_t)n * HH * WW;
    const float* __restrict__ xp = x + gbase + t;
    const int st = swz(t);

    const bool interior = (h0 - RH >= 0) && (h0 + CH - 1 + RH + 1 <= HH - 1);

    // ---- init sliding sum for output row h0: rows [h0-RH, h0+RH] clamped ----
    float s;
    if (interior) {
        float s0 = 0.f, s1 = 0.f, s2 = 0.f, s3 = 0.f;
        const float* p = xp + (size_t)(h0 - RH) * WW;
        #pragma unroll
        for (int r = 0; r < 76; r += 4) {
            s0 += p[(size_t)(r + 0) * WW];
            s1 += p[(size_t)(r + 1) * WW];
            s2 += p[(size_t)(r + 2) * WW];
            s3 += p[(size_t)(r + 3) * WW];
        }
        s = (s0 + s1) + (s2 + s3)
          + p[(size_t)76 * WW] + p[(size_t)77 * WW] + p[(size_t)78 * WW];
    } else {
        s = 0.f;
        int lo = h0 - RH; if (lo < 0) lo = 0;
        int hi = h0 + RH; if (hi > HH - 1) hi = HH - 1;
        for (int r = lo; r <= hi; ++r) s += xp[(size_t)r * WW];
    }

    // ---- 4 sub-stripes: fill -> barrier -> scan+epilogue (double-buffered) ---
    #pragma unroll
    for (int sub = 0; sub < NSUB; ++sub) {
        float* __restrict__ buf = smemC + ((sub & 1) ? (TH * WW) : 0);
        const int hr0 = h0 + sub * TH;

        if (interior) {
            #pragma unroll
            for (int k = 0; k < TH; ++k) {
                buf[(k << 9) + st] = s;
                s += xp[(size_t)(hr0 + k + RH + 1) * WW]
                   - xp[(size_t)(hr0 + k - RH) * WW];
            }
        } else {
            #pragma unroll
            for (int k = 0; k < TH; ++k) {
                buf[(k << 9) + st] = s;
                int add = hr0 + k + RH + 1;
                int sb  = hr0 + k - RH;
                float a = (add < HH) ? xp[(size_t)add * WW] : 0.f;
                float b = (sb >= 0)  ? xp[(size_t)sb * WW]  : 0.f;
                s += a - b;
            }
        }
        __syncthreads();   // buf filled; also separates prior epilogue reads of
                           // this buffer (2 sub-stripes ago) from these writes
        scan_and_epilogue(buf, x, out, gbase, hr0, lane, wrp);
    }
}

extern "C" void kernel_launch(void* const* d_in, const int* in_sizes, int n_in,
                              void* d_out, int out_size) {
    const float* x = (const float*)d_in[0];
    float* out = (float*)d_out;

    const int smem_bytes = 2 * TH * WW * (int)sizeof(float);   // 64 KB
    cudaFuncSetAttribute(sliding_mean_fused,
                         cudaFuncAttributeMaxDynamicSharedMemorySize, smem_bytes);

    sliding_mean_fused<<<NB * (HH / CH), 512, smem_bytes>>>(x, out);
}